// round 3
// baseline (speedup 1.0000x reference)
#include <cuda_runtime.h>
#include <math.h>

// Problem constants (shapes fixed by the dataset)
#define NNODES 100000
#define NEDGES 1000000
#define ET     (NEDGES + NNODES)   // edges + self loops
#define DHEAD  48
#define GBATCH 64
#define FCDIM  192
#define OUTDIM 96
#define HDMAX  192

// ---------------- device scratch (static, no allocations) ----------------
__device__ __align__(16) float    g_bufA[(size_t)NNODES * HDMAX];  // h (post-GEMM)
__device__ __align__(16) float    g_bufB[(size_t)NNODES * HDMAX];  // aggregated out
__device__ __align__(16) float    g_asrc[NNODES * 4];
__device__ __align__(16) float    g_adst[NNODES * 4];
__device__ __align__(16) unsigned g_menc[NNODES * 4];              // segment max (encoded)
__device__ __align__(16) float    g_denom[NNODES * 4];
__device__ __align__(16) float    g_ew[(size_t)ET * 4];            // per-edge e / w
__device__ __align__(16) int      g_src[ET];
__device__ __align__(16) int      g_dst[ET];
__device__ __align__(16) float    g_sums[GBATCH * OUTDIM];
__device__ __align__(16) float    g_cnt[GBATCH];

// ordered-uint encoding for float atomicMax (total order incl. negatives)
__device__ __forceinline__ unsigned fenc(float x) {
    unsigned u = __float_as_uint(x);
    return (u & 0x80000000u) ? ~u : (u | 0x80000000u);
}
__device__ __forceinline__ float fdec(unsigned u) {
    return (u & 0x80000000u) ? __uint_as_float(u & 0x7fffffffu) : __uint_as_float(~u);
}

__device__ __forceinline__ void red_add_v4(float* p, float4 v) {
    asm volatile("red.global.add.v4.f32 [%0], {%1,%2,%3,%4};"
                 :: "l"(p), "f"(v.x), "f"(v.y), "f"(v.z), "f"(v.w) : "memory");
}

// ---------------- edge list build (int32 indices, append self loops) ------
// NOTE: JAX x64 is disabled by default -> edge_index/batch arrive as int32.
__global__ void conv_edges(const int* __restrict__ ei) {
    int e = blockIdx.x * blockDim.x + threadIdx.x;
    if (e >= ET) return;
    if (e < NEDGES) {
        g_src[e] = ei[e];
        g_dst[e] = ei[NEDGES + e];
    } else {
        g_src[e] = e - NEDGES;
        g_dst[e] = e - NEDGES;
    }
}

// ---------------- tiled fp32 GEMM: C[M,Nc] = A[M,K] @ B[K,Nc] -------------
// BM=64 BN=64 BK=16, 256 threads, 4x4 per thread
__global__ void sgemm64(const float* __restrict__ A, const float* __restrict__ B,
                        float* __restrict__ C, int M, int K, int Nc) {
    __shared__ float As[16][64];   // [k][m]  (transposed on load)
    __shared__ float Bs[16][64];   // [k][n]
    const int t  = threadIdx.x;
    const int tx = t & 15, ty = t >> 4;
    const int rowBase = blockIdx.x * 64;
    const int colBase = blockIdx.y * 64;

    float acc[4][4];
#pragma unroll
    for (int i = 0; i < 4; i++)
#pragma unroll
        for (int j = 0; j < 4; j++) acc[i][j] = 0.f;

    for (int k0 = 0; k0 < K; k0 += 16) {
        {   // A tile: 64 rows x 16 k, float4 per thread
            int r = t >> 2;
            int c = (t & 3) << 2;
            int gr = rowBase + r;
            float4 v = make_float4(0.f, 0.f, 0.f, 0.f);
            if (gr < M) v = *(const float4*)(A + (size_t)gr * K + k0 + c);
            As[c + 0][r] = v.x; As[c + 1][r] = v.y; As[c + 2][r] = v.z; As[c + 3][r] = v.w;
        }
        {   // B tile: 16 k x 64 cols, float4 per thread
            int r = t >> 4;
            int c = (t & 15) << 2;
            int gc = colBase + c;
            float4 v = make_float4(0.f, 0.f, 0.f, 0.f);
            if (gc < Nc) v = *(const float4*)(B + (size_t)(k0 + r) * Nc + gc);
            *(float4*)&Bs[r][c] = v;
        }
        __syncthreads();
#pragma unroll
        for (int kk = 0; kk < 16; kk++) {
            float4 a4 = *(const float4*)&As[kk][ty << 2];
            float4 b4 = *(const float4*)&Bs[kk][tx << 2];
            acc[0][0] += a4.x * b4.x; acc[0][1] += a4.x * b4.y; acc[0][2] += a4.x * b4.z; acc[0][3] += a4.x * b4.w;
            acc[1][0] += a4.y * b4.x; acc[1][1] += a4.y * b4.y; acc[1][2] += a4.y * b4.z; acc[1][3] += a4.y * b4.w;
            acc[2][0] += a4.z * b4.x; acc[2][1] += a4.z * b4.y; acc[2][2] += a4.z * b4.z; acc[2][3] += a4.z * b4.w;
            acc[3][0] += a4.w * b4.x; acc[3][1] += a4.w * b4.y; acc[3][2] += a4.w * b4.z; acc[3][3] += a4.w * b4.w;
        }
        __syncthreads();
    }

#pragma unroll
    for (int i = 0; i < 4; i++) {
        int gr = rowBase + (ty << 2) + i;
        if (gr >= M) continue;
        int gc = colBase + (tx << 2);
        if (gc < Nc) {
            float4 v = make_float4(acc[i][0], acc[i][1], acc[i][2], acc[i][3]);
            *(float4*)(C + (size_t)gr * Nc + gc) = v;
        }
    }
}

// ---------------- attention scalars: a_src/a_dst = sum_d h*att -----------
__global__ void calc_a(const float* __restrict__ h, const float* __restrict__ att_src,
                       const float* __restrict__ att_dst, int H) {
    int i = blockIdx.x * blockDim.x + threadIdx.x;  // n*H + hh
    if (i >= NNODES * H) return;
    int hh = i % H, n = i / H;
    const float4* hp = (const float4*)(h + (size_t)n * H * DHEAD + hh * DHEAD);
    const float4* as = (const float4*)(att_src + hh * DHEAD);
    const float4* ad = (const float4*)(att_dst + hh * DHEAD);
    float s = 0.f, d = 0.f;
#pragma unroll
    for (int q = 0; q < DHEAD / 4; q++) {
        float4 hv = hp[q], a = as[q], b = ad[q];
        s += hv.x * a.x + hv.y * a.y + hv.z * a.z + hv.w * a.w;
        d += hv.x * b.x + hv.y * b.y + hv.z * b.z + hv.w * b.w;
    }
    g_asrc[i] = s;
    g_adst[i] = d;
}

// ---------------- edge pass 1: e = leakyrelu(asrc[s]+adst[d]); seg max ----
__global__ void edge_pass1(int H) {
    int e = blockIdx.x * blockDim.x + threadIdx.x;
    if (e >= ET) return;
    int s = g_src[e], d = g_dst[e];
    for (int hh = 0; hh < H; hh++) {
        float ev = g_asrc[s * H + hh] + g_adst[d * H + hh];
        ev = (ev > 0.f) ? ev : 0.2f * ev;
        g_ew[(size_t)e * H + hh] = ev;
        atomicMax(&g_menc[d * H + hh], fenc(ev));
    }
}

// ---------------- edge pass 2: w = exp(e - m[d]); seg sum -----------------
__global__ void edge_pass2(int H) {
    int e = blockIdx.x * blockDim.x + threadIdx.x;
    if (e >= ET) return;
    int d = g_dst[e];
    for (int hh = 0; hh < H; hh++) {
        float m = fdec(g_menc[d * H + hh]);
        float w = __expf(g_ew[(size_t)e * H + hh] - m);
        g_ew[(size_t)e * H + hh] = w;
        atomicAdd(&g_denom[d * H + hh], w);
    }
}

// ---------------- edge pass 3: out[dst] += h[src] * w/(denom[dst]+eps) ----
__global__ void edge_pass3(const float* __restrict__ h, float* __restrict__ out,
                           int HD, int H, int total) {
    int idx = blockIdx.x * blockDim.x + threadIdx.x;
    if (idx >= total) return;
    int nj = HD >> 2;
    int e  = idx / nj;
    int j  = (idx - e * nj) << 2;
    int head = j / DHEAD;
    int s = g_src[e], d = g_dst[e];
    float w = g_ew[(size_t)e * H + head];
    float alpha = w / (g_denom[d * H + head] + 1e-16f);
    float4 hv = *(const float4*)(h + (size_t)s * HD + j);
    float4 v = make_float4(hv.x * alpha, hv.y * alpha, hv.z * alpha, hv.w * alpha);
    red_add_v4(out + (size_t)d * HD + j, v);
}

// ---------------- out = relu(out + bias) ----------------------------------
__global__ void relu_bias(float* __restrict__ out, const float* __restrict__ bias,
                          int HD, int total) {
    int idx = blockIdx.x * blockDim.x + threadIdx.x;
    if (idx >= total) return;
    float v = out[idx] + bias[idx % HD];
    out[idx] = fmaxf(v, 0.f);
}

// ---------------- pooling: segment mean over graphs -----------------------
__global__ void pool_kernel(const float* __restrict__ x, const int* __restrict__ batch) {
    int idx = blockIdx.x * blockDim.x + threadIdx.x;  // n * 24 + j4
    int n = idx / (OUTDIM / 4);
    if (n >= NNODES) return;
    int j = (idx - n * (OUTDIM / 4)) << 2;
    int b = batch[n];
    float4 v = *(const float4*)(x + (size_t)n * OUTDIM + j);
    red_add_v4(&g_sums[b * OUTDIM + j], v);
    if (j == 0) atomicAdd(&g_cnt[b], 1.f);
}

// ---------------- final MLP: pooled -> fc1(relu) -> fc2 -------------------
__global__ void fc_kernel(const float* __restrict__ fcW1, const float* __restrict__ fcb1,
                          const float* __restrict__ fcW2, const float* __restrict__ fcb2,
                          float* __restrict__ out) {
    __shared__ float pooled[OUTDIM];
    __shared__ float h1[FCDIM];
    int g = blockIdx.x, t = threadIdx.x;  // 192 threads
    if (t < OUTDIM) {
        float c = fmaxf(g_cnt[g], 1.f);
        pooled[t] = g_sums[g * OUTDIM + t] / c;
    }
    __syncthreads();
    float acc = fcb1[t];
    for (int i = 0; i < OUTDIM; i++) acc += pooled[i] * fcW1[(size_t)i * FCDIM + t];
    h1[t] = fmaxf(acc, 0.f);
    __syncthreads();
    if (t < OUTDIM) {
        float a = fcb2[t];
        for (int i = 0; i < FCDIM; i++) a += h1[i] * fcW2[(size_t)i * OUTDIM + t];
        out[g * OUTDIM + t] = a;
    }
}

// ==========================================================================
extern "C" void kernel_launch(void* const* d_in, const int* in_sizes, int n_in,
                              void* d_out, int out_size) {
    const float* x     = (const float*)d_in[0];
    const int*   ei    = (const int*)d_in[1];     // int32 (JAX x64 disabled)
    const int*   batch = (const int*)d_in[2];     // int32
    const float* W[3]    = { (const float*)d_in[3],  (const float*)d_in[7],  (const float*)d_in[11] };
    const float* asv[3]  = { (const float*)d_in[4],  (const float*)d_in[8],  (const float*)d_in[12] };
    const float* adv[3]  = { (const float*)d_in[5],  (const float*)d_in[9],  (const float*)d_in[13] };
    const float* bias[3] = { (const float*)d_in[6],  (const float*)d_in[10], (const float*)d_in[14] };
    const float* fcW1 = (const float*)d_in[15];
    const float* fcb1 = (const float*)d_in[16];
    const float* fcW2 = (const float*)d_in[17];
    const float* fcb2 = (const float*)d_in[18];
    float* out = (float*)d_out;

    const int H[3]   = { 4, 2, 2 };
    const int INC[3] = { 128, 192, 96 };
    const int HD[3]  = { 192, 96, 96 };

    float *bufA, *bufB, *denom, *sums, *cnt;
    unsigned* menc;
    cudaGetSymbolAddress((void**)&bufA,  g_bufA);
    cudaGetSymbolAddress((void**)&bufB,  g_bufB);
    cudaGetSymbolAddress((void**)&menc,  g_menc);
    cudaGetSymbolAddress((void**)&denom, g_denom);
    cudaGetSymbolAddress((void**)&sums,  g_sums);
    cudaGetSymbolAddress((void**)&cnt,   g_cnt);

    conv_edges<<<(ET + 255) / 256, 256>>>(ei);

    const float* xin = x;
    for (int l = 0; l < 3; l++) {
        dim3 grid((NNODES + 63) / 64, (HD[l] + 63) / 64);
        sgemm64<<<grid, 256>>>(xin, W[l], bufA, NNODES, INC[l], HD[l]);

        calc_a<<<(NNODES * H[l] + 255) / 256, 256>>>(bufA, asv[l], adv[l], H[l]);

        cudaMemsetAsync(menc,  0, (size_t)NNODES * H[l] * sizeof(unsigned));
        cudaMemsetAsync(denom, 0, (size_t)NNODES * H[l] * sizeof(float));
        cudaMemsetAsync(bufB,  0, (size_t)NNODES * HD[l] * sizeof(float));

        edge_pass1<<<(ET + 255) / 256, 256>>>(H[l]);
        edge_pass2<<<(ET + 255) / 256, 256>>>(H[l]);

        int total3 = ET * (HD[l] / 4);
        edge_pass3<<<(total3 + 255) / 256, 256>>>(bufA, bufB, HD[l], H[l], total3);

        int totalR = NNODES * HD[l];
        relu_bias<<<(totalR + 255) / 256, 256>>>(bufB, bias[l], HD[l], totalR);

        xin = bufB;
    }

    cudaMemsetAsync(sums, 0, GBATCH * OUTDIM * sizeof(float));
    cudaMemsetAsync(cnt,  0, GBATCH * sizeof(float));
    int totalP = NNODES * (OUTDIM / 4);
    pool_kernel<<<(totalP + 255) / 256, 256>>>(bufB, batch);

    fc_kernel<<<GBATCH, FCDIM>>>(fcW1, fcb1, fcW2, fcb2, out);
}

// round 4
// speedup vs baseline: 1.7517x; 1.7517x over previous
#include <cuda_runtime.h>
#include <math.h>
#include <string.h>

// Problem constants (shapes fixed by the dataset)
#define NNODES 100000
#define NEDGES 1000000
#define ET     (NEDGES + NNODES)   // edges + self loops
#define DHEAD  48
#define GBATCH 64
#define FCDIM  192
#define OUTDIM 96
#define HDMAX  192
#define SCAN_B 512
#define NSCANB ((NNODES + SCAN_B - 1) / SCAN_B)   // 196

// ---------------- device scratch (static, no allocations) ----------------
__device__ __align__(16) float g_bufA[(size_t)NNODES * HDMAX];   // h (post-GEMM)
__device__ __align__(16) float g_bufB[(size_t)NNODES * HDMAX];   // aggregated out
__device__ __align__(16) float g_asrc[NNODES * 4];
__device__ __align__(16) float g_adst[NNODES * 4];
__device__ __align__(16) float g_denom[NNODES * 4];              // 1/(sum+eps)
__device__ __align__(16) float g_ew[(size_t)ET * 4];             // unnormalized softmax w (CSR order)
__device__ __align__(16) int   g_src[ET];
__device__ __align__(16) int   g_dst[ET];
__device__ __align__(16) int   g_deg[NNODES];
__device__ __align__(16) int   g_off[NNODES + 1];                // CSR row offsets (by dst)
__device__ __align__(16) int   g_cursor[NNODES];
__device__ __align__(16) int   g_cs[ET];                         // CSR src per position
__device__ __align__(16) int   g_bsum[NSCANB];
__device__ __align__(16) float g_sums[GBATCH * OUTDIM];
__device__ __align__(16) float g_cnt[GBATCH];

__device__ __forceinline__ void red_add_v4(float* p, float4 v) {
    asm volatile("red.global.add.v4.f32 [%0], {%1,%2,%3,%4};"
                 :: "l"(p), "f"(v.x), "f"(v.y), "f"(v.z), "f"(v.w) : "memory");
}

union U64F2 { unsigned long long u; float2 f; };

// ================= CSR build =============================================
__global__ void conv_edges(const int* __restrict__ ei) {
    int e = blockIdx.x * blockDim.x + threadIdx.x;
    if (e >= ET) return;
    int s, d;
    if (e < NEDGES) { s = ei[e]; d = ei[NEDGES + e]; }
    else            { s = e - NEDGES; d = s; }
    g_src[e] = s;
    g_dst[e] = d;
    atomicAdd(&g_deg[d], 1);
}

__global__ void scan_local() {
    __shared__ int sm[SCAN_B];
    int i = blockIdx.x * SCAN_B + threadIdx.x;
    int v = (i < NNODES) ? g_deg[i] : 0;
    sm[threadIdx.x] = v;
    __syncthreads();
    for (int ofs = 1; ofs < SCAN_B; ofs <<= 1) {
        int add = (threadIdx.x >= ofs) ? sm[threadIdx.x - ofs] : 0;
        __syncthreads();
        sm[threadIdx.x] += add;
        __syncthreads();
    }
    if (i < NNODES) g_off[i] = sm[threadIdx.x] - v;   // exclusive
    if (threadIdx.x == SCAN_B - 1) g_bsum[blockIdx.x] = sm[SCAN_B - 1];
}

__global__ void scan_block() {
    int acc = 0;
    for (int b = 0; b < NSCANB; b++) { int v = g_bsum[b]; g_bsum[b] = acc; acc += v; }
    g_off[NNODES] = ET;
}

__global__ void scan_add() {
    int i = blockIdx.x * SCAN_B + threadIdx.x;
    if (i < NNODES) g_off[i] += g_bsum[blockIdx.x];
}

__global__ void scatter_edges() {
    int e = blockIdx.x * blockDim.x + threadIdx.x;
    if (e >= ET) return;
    int d = g_dst[e];
    int pos = g_off[d] + atomicAdd(&g_cursor[d], 1);
    g_cs[pos] = g_src[e];
}

// ================= GEMM with packed f32x2 FMA =============================
// C[M,Nc] = A[M,K] @ B[K,Nc].  BM=128, BN=96, BK=16, 256 threads.
// Each thread: 4 row-pairs x 6 cols, accumulated as f32x2.
#define BM 128
#define BN 96
#define BK 16

__global__ __launch_bounds__(256) void sgemm_f32x2(
    const float* __restrict__ A, const float* __restrict__ B,
    float* __restrict__ C, int M, int K, int Nc) {
    __shared__ float  As[BK][BM];    // [k][m] (transposed)
    __shared__ float2 Bs[BK][BN];    // duplicated pairs (b,b)

    const int t  = threadIdx.x;
    const int tx = t & 15;           // col group (6 cols)
    const int ty = t >> 4;           // row group (8 rows = 4 pairs)
    const int rowBase = blockIdx.x * BM;
    const int colBase = blockIdx.y * BN;

    unsigned long long acc[4][6];
#pragma unroll
    for (int r = 0; r < 4; r++)
#pragma unroll
        for (int c = 0; c < 6; c++) acc[r][c] = 0ULL;

    for (int k0 = 0; k0 < K; k0 += BK) {
        // --- load A tile (128x16), transposed to As[k][m] ---
#pragma unroll
        for (int it = 0; it < 2; it++) {
            int idx = t + it * 256;          // 0..511
            int r = idx >> 2;
            int c = (idx & 3) << 2;
            int gr = rowBase + r;
            float4 v = make_float4(0.f, 0.f, 0.f, 0.f);
            if (gr < M) v = *(const float4*)(A + (size_t)gr * K + k0 + c);
            As[c + 0][r] = v.x; As[c + 1][r] = v.y; As[c + 2][r] = v.z; As[c + 3][r] = v.w;
        }
        // --- load B tile (16x96), duplicated into float2 ---
#pragma unroll
        for (int idx = t; idx < BK * BN; idx += 256) {
            int k = idx / BN;
            int n = idx - k * BN;
            float v = B[(size_t)(k0 + k) * Nc + colBase + n];
            Bs[k][n] = make_float2(v, v);
        }
        __syncthreads();

#pragma unroll
        for (int kk = 0; kk < BK; kk++) {
            ulonglong2 aP0 = *(const ulonglong2*)&As[kk][ty * 8];       // pairs (r0,r1),(r2,r3)
            ulonglong2 aP1 = *(const ulonglong2*)&As[kk][ty * 8 + 4];   // pairs (r4,r5),(r6,r7)
            ulonglong2 b01 = *(const ulonglong2*)&Bs[kk][tx * 6];
            ulonglong2 b23 = *(const ulonglong2*)&Bs[kk][tx * 6 + 2];
            ulonglong2 b45 = *(const ulonglong2*)&Bs[kk][tx * 6 + 4];
            unsigned long long ap[4] = { aP0.x, aP0.y, aP1.x, aP1.y };
            unsigned long long bp[6] = { b01.x, b01.y, b23.x, b23.y, b45.x, b45.y };
#pragma unroll
            for (int r = 0; r < 4; r++)
#pragma unroll
                for (int c = 0; c < 6; c++)
                    asm("fma.rn.f32x2 %0, %1, %2, %3;"
                        : "=l"(acc[r][c]) : "l"(ap[r]), "l"(bp[c]), "l"(acc[r][c]));
        }
        __syncthreads();
    }

    // --- epilogue ---
#pragma unroll
    for (int r = 0; r < 4; r++) {
        int gr0 = rowBase + ty * 8 + 2 * r;
#pragma unroll
        for (int c = 0; c < 6; c++) {
            U64F2 u; u.u = acc[r][c];
            int gc = colBase + tx * 6 + c;
            if (gr0 < M)     C[(size_t)gr0 * Nc + gc]       = u.f.x;
            if (gr0 + 1 < M) C[(size_t)(gr0 + 1) * Nc + gc] = u.f.y;
        }
    }
}

// ================= attention scalars ======================================
__global__ void calc_a(const float* __restrict__ h, const float* __restrict__ att_src,
                       const float* __restrict__ att_dst, int H) {
    int i = blockIdx.x * blockDim.x + threadIdx.x;  // n*H + hh
    if (i >= NNODES * H) return;
    int hh = i % H, n = i / H;
    const float4* hp = (const float4*)(h + (size_t)n * H * DHEAD + hh * DHEAD);
    const float4* as = (const float4*)(att_src + hh * DHEAD);
    const float4* ad = (const float4*)(att_dst + hh * DHEAD);
    float s = 0.f, d = 0.f;
#pragma unroll
    for (int q = 0; q < DHEAD / 4; q++) {
        float4 hv = hp[q], a = as[q], b = ad[q];
        s += hv.x * a.x + hv.y * a.y + hv.z * a.z + hv.w * a.w;
        d += hv.x * b.x + hv.y * b.y + hv.z * b.z + hv.w * b.w;
    }
    g_asrc[i] = s;
    g_adst[i] = d;
}

// ================= fused softmax over incoming edges (CSR, no atomics) ====
__global__ void attn_softmax(int H) {
    int i = blockIdx.x * blockDim.x + threadIdx.x;  // n*H + hh
    if (i >= NNODES * H) return;
    int n = i / H, hh = i - n * H;
    int start = g_off[n], end = g_off[n + 1];
    float ad = g_adst[i];
    float m = -1e30f;
    for (int p = start; p < end; p++) {
        float v = g_asrc[g_cs[p] * H + hh] + ad;
        v = (v > 0.f) ? v : 0.2f * v;
        m = fmaxf(m, v);
    }
    float sum = 0.f;
    for (int p = start; p < end; p++) {
        float v = g_asrc[g_cs[p] * H + hh] + ad;
        v = (v > 0.f) ? v : 0.2f * v;
        float w = __expf(v - m);
        g_ew[(size_t)p * H + hh] = w;
        sum += w;
    }
    g_denom[i] = 1.f / (sum + 1e-16f);
}

// ================= gather aggregation + bias + relu (no atomics) ==========
__global__ void aggregate(const float* __restrict__ h, float* __restrict__ out,
                          const float* __restrict__ bias, int HD, int H, int total) {
    int idx = blockIdx.x * blockDim.x + threadIdx.x;  // n * (HD/4) + j4
    if (idx >= total) return;
    int nj = HD >> 2;
    int n = idx / nj;
    int j = (idx - n * nj) << 2;
    int head = j / DHEAD;
    int start = g_off[n], end = g_off[n + 1];
    float4 acc = make_float4(0.f, 0.f, 0.f, 0.f);
    for (int p = start; p < end; p++) {
        int s = g_cs[p];
        float w = g_ew[(size_t)p * H + head];
        float4 hv = *(const float4*)(h + (size_t)s * HD + j);
        acc.x += hv.x * w; acc.y += hv.y * w; acc.z += hv.z * w; acc.w += hv.w * w;
    }
    float inv = g_denom[n * H + head];
    float4 b4 = *(const float4*)(bias + j);
    float4 o;
    o.x = fmaxf(acc.x * inv + b4.x, 0.f);
    o.y = fmaxf(acc.y * inv + b4.y, 0.f);
    o.z = fmaxf(acc.z * inv + b4.z, 0.f);
    o.w = fmaxf(acc.w * inv + b4.w, 0.f);
    *(float4*)(out + (size_t)n * HD + j) = o;
}

// ================= pooling + MLP ==========================================
__global__ void pool_kernel(const float* __restrict__ x, const int* __restrict__ batch) {
    int idx = blockIdx.x * blockDim.x + threadIdx.x;  // n * 24 + j4
    int n = idx / (OUTDIM / 4);
    if (n >= NNODES) return;
    int j = (idx - n * (OUTDIM / 4)) << 2;
    int b = batch[n];
    float4 v = *(const float4*)(x + (size_t)n * OUTDIM + j);
    red_add_v4(&g_sums[b * OUTDIM + j], v);
    if (j == 0) atomicAdd(&g_cnt[b], 1.f);
}

__global__ void fc_kernel(const float* __restrict__ fcW1, const float* __restrict__ fcb1,
                          const float* __restrict__ fcW2, const float* __restrict__ fcb2,
                          float* __restrict__ out) {
    __shared__ float pooled[OUTDIM];
    __shared__ float h1[FCDIM];
    int g = blockIdx.x, t = threadIdx.x;  // 192 threads
    if (t < OUTDIM) {
        float c = fmaxf(g_cnt[g], 1.f);
        pooled[t] = g_sums[g * OUTDIM + t] / c;
    }
    __syncthreads();
    float acc = fcb1[t];
    for (int i = 0; i < OUTDIM; i++) acc += pooled[i] * fcW1[(size_t)i * FCDIM + t];
    h1[t] = fmaxf(acc, 0.f);
    __syncthreads();
    if (t < OUTDIM) {
        float a = fcb2[t];
        for (int i = 0; i < FCDIM; i++) a += h1[i] * fcW2[(size_t)i * OUTDIM + t];
        out[g * OUTDIM + t] = a;
    }
}

// ==========================================================================
extern "C" void kernel_launch(void* const* d_in, const int* in_sizes, int n_in,
                              void* d_out, int out_size) {
    const float* x     = (const float*)d_in[0];
    const int*   ei    = (const int*)d_in[1];     // int32 (JAX x64 disabled)
    const int*   batch = (const int*)d_in[2];     // int32
    const float* W[3]    = { (const float*)d_in[3],  (const float*)d_in[7],  (const float*)d_in[11] };
    const float* asv[3]  = { (const float*)d_in[4],  (const float*)d_in[8],  (const float*)d_in[12] };
    const float* adv[3]  = { (const float*)d_in[5],  (const float*)d_in[9],  (const float*)d_in[13] };
    const float* bias[3] = { (const float*)d_in[6],  (const float*)d_in[10], (const float*)d_in[14] };
    const float* fcW1 = (const float*)d_in[15];
    const float* fcb1 = (const float*)d_in[16];
    const float* fcW2 = (const float*)d_in[17];
    const float* fcb2 = (const float*)d_in[18];
    float* out = (float*)d_out;

    const int H[3]   = { 4, 2, 2 };
    const int INC[3] = { 128, 192, 96 };
    const int HD[3]  = { 192, 96, 96 };

    float *bufA, *bufB, *sums, *cnt;
    int *deg, *cursor;
    cudaGetSymbolAddress((void**)&bufA,   g_bufA);
    cudaGetSymbolAddress((void**)&bufB,   g_bufB);
    cudaGetSymbolAddress((void**)&sums,   g_sums);
    cudaGetSymbolAddress((void**)&cnt,    g_cnt);
    cudaGetSymbolAddress((void**)&deg,    g_deg);
    cudaGetSymbolAddress((void**)&cursor, g_cursor);

    // ---- CSR build (once per launch; reused by all 3 layers) ----
    cudaMemsetAsync(deg,    0, NNODES * sizeof(int));
    cudaMemsetAsync(cursor, 0, NNODES * sizeof(int));
    conv_edges<<<(ET + 255) / 256, 256>>>(ei);
    scan_local<<<NSCANB, SCAN_B>>>();
    scan_block<<<1, 1>>>();
    scan_add<<<NSCANB, SCAN_B>>>();
    scatter_edges<<<(ET + 255) / 256, 256>>>();

    const float* xin = x;
    for (int l = 0; l < 3; l++) {
        dim3 grid((NNODES + BM - 1) / BM, HD[l] / BN);
        sgemm_f32x2<<<grid, 256>>>(xin, W[l], bufA, NNODES, INC[l], HD[l]);

        calc_a<<<(NNODES * H[l] + 255) / 256, 256>>>(bufA, asv[l], adv[l], H[l]);

        attn_softmax<<<(NNODES * H[l] + 255) / 256, 256>>>(H[l]);

        int total = NNODES * (HD[l] / 4);
        aggregate<<<(total + 255) / 256, 256>>>(bufA, bufB, bias[l], HD[l], H[l], total);

        xin = bufB;
    }

    cudaMemsetAsync(sums, 0, GBATCH * OUTDIM * sizeof(float));
    cudaMemsetAsync(cnt,  0, GBATCH * sizeof(float));
    int totalP = NNODES * (OUTDIM / 4);
    pool_kernel<<<(totalP + 255) / 256, 256>>>(bufB, batch);

    fc_kernel<<<GBATCH, FCDIM>>>(fcW1, fcb1, fcW2, fcb2, out);
}

// round 5
// speedup vs baseline: 1.7761x; 1.0139x over previous
#include <cuda_runtime.h>
#include <math.h>

// Problem constants (shapes fixed by the dataset)
#define NNODES 100000
#define NEDGES 1000000
#define ET     (NEDGES + NNODES)   // edges + self loops
#define DHEAD  48
#define GBATCH 64
#define FCDIM  192
#define OUTDIM 96
#define HDMAX  192
#define SCAN_B 512
#define NSCANB ((NNODES + SCAN_B - 1) / SCAN_B)   // 196

// ---------------- device scratch (static, no allocations) ----------------
__device__ __align__(16) float g_bufA[(size_t)NNODES * HDMAX];   // h (post-GEMM)
__device__ __align__(16) float g_bufB[(size_t)NNODES * HDMAX];   // aggregated out
__device__ __align__(16) float g_asrc[NNODES * 4];
__device__ __align__(16) float g_adst[NNODES * 4];
__device__ __align__(16) float g_denom[NNODES * 4];              // 1/(sum+eps)
__device__ __align__(16) float g_ew[(size_t)ET * 4];             // unnormalized softmax w (CSR)
__device__ __align__(16) int   g_src[ET];
__device__ __align__(16) int   g_dst[ET];
__device__ __align__(16) int   g_deg[NNODES];
__device__ __align__(16) int   g_off[NNODES + 1];                // CSR row offsets (by dst)
__device__ __align__(16) int   g_cursor[NNODES];
__device__ __align__(16) int   g_cs[ET];                         // CSR src per position
__device__ __align__(16) int   g_bsum[NSCANB];
__device__ __align__(16) float g_sums[GBATCH * OUTDIM];
__device__ __align__(16) float g_cnt[GBATCH];

__device__ __forceinline__ void red_add_v4(float* p, float4 v) {
    asm volatile("red.global.add.v4.f32 [%0], {%1,%2,%3,%4};"
                 :: "l"(p), "f"(v.x), "f"(v.y), "f"(v.z), "f"(v.w) : "memory");
}

union U64F2 { unsigned long long u; float2 f; };

// ================= CSR build =============================================
__global__ void conv_edges(const int* __restrict__ ei) {
    int e = blockIdx.x * blockDim.x + threadIdx.x;
    if (e >= ET) return;
    int s, d;
    if (e < NEDGES) { s = ei[e]; d = ei[NEDGES + e]; }
    else            { s = e - NEDGES; d = s; }
    g_src[e] = s;
    g_dst[e] = d;
    atomicAdd(&g_deg[d], 1);
}

__global__ void scan_local() {
    __shared__ int sm[SCAN_B];
    int i = blockIdx.x * SCAN_B + threadIdx.x;
    int v = (i < NNODES) ? g_deg[i] : 0;
    sm[threadIdx.x] = v;
    __syncthreads();
    for (int ofs = 1; ofs < SCAN_B; ofs <<= 1) {
        int add = (threadIdx.x >= ofs) ? sm[threadIdx.x - ofs] : 0;
        __syncthreads();
        sm[threadIdx.x] += add;
        __syncthreads();
    }
    if (i < NNODES) g_off[i] = sm[threadIdx.x] - v;   // exclusive
    if (threadIdx.x == SCAN_B - 1) g_bsum[blockIdx.x] = sm[SCAN_B - 1];
}

__global__ void scan_block() {
    int acc = 0;
    for (int b = 0; b < NSCANB; b++) { int v = g_bsum[b]; g_bsum[b] = acc; acc += v; }
    g_off[NNODES] = ET;
}

__global__ void scan_add() {
    int i = blockIdx.x * SCAN_B + threadIdx.x;
    if (i < NNODES) g_off[i] += g_bsum[blockIdx.x];
}

__global__ void scatter_edges() {
    int e = blockIdx.x * blockDim.x + threadIdx.x;
    if (e >= ET) return;
    int d = g_dst[e];
    int pos = g_off[d] + atomicAdd(&g_cursor[d], 1);
    g_cs[pos] = g_src[e];
}

// ================= GEMM with packed f32x2 FMA =============================
// C[M,Nc] = A[M,K] @ B[K,Nc].  BM=192, BN=96, BK=16, 256 threads.
// Each thread: 6 row-pairs (12 rows) x 6 cols. B replicated in-register.
#define BM 192
#define BN 96
#define BK 16

__global__ __launch_bounds__(256) void sgemm_f32x2(
    const float* __restrict__ A, const float* __restrict__ B,
    float* __restrict__ C, int M, int K, int Nc) {
    __shared__ float As[BK][BM];    // [k][m] (transposed) -> row-pairs contiguous
    __shared__ float Bs[BK][BN];    // plain floats

    const int t  = threadIdx.x;
    const int tx = t & 15;           // col group (6 cols)
    const int ty = t >> 4;           // row group (12 rows = 6 pairs)
    const int rowBase = blockIdx.x * BM;
    const int colBase = blockIdx.y * BN;

    unsigned long long acc[6][6];
#pragma unroll
    for (int r = 0; r < 6; r++)
#pragma unroll
        for (int c = 0; c < 6; c++) acc[r][c] = 0ULL;

    for (int k0 = 0; k0 < K; k0 += BK) {
        // --- load A tile (192x16), transposed to As[k][m] ---
#pragma unroll
        for (int it = 0; it < 3; it++) {
            int idx = t + it * 256;          // 0..767 (192 rows * 4 float4)
            int r = idx >> 2;
            int c = (idx & 3) << 2;
            int gr = rowBase + r;
            float4 v = make_float4(0.f, 0.f, 0.f, 0.f);
            if (gr < M) v = *(const float4*)(A + (size_t)gr * K + k0 + c);
            As[c + 0][r] = v.x; As[c + 1][r] = v.y; As[c + 2][r] = v.z; As[c + 3][r] = v.w;
        }
        // --- load B tile (16x96) ---
#pragma unroll
        for (int idx = t; idx < BK * BN; idx += 256) {
            int k = idx / BN;
            int n = idx - k * BN;
            Bs[k][n] = B[(size_t)(k0 + k) * Nc + colBase + n];
        }
        __syncthreads();

#pragma unroll
        for (int kk = 0; kk < BK; kk++) {
            // A row-pairs: 3 x 16B loads give 6 (r0,r1) f32x2 operands directly
            ulonglong2 aP0 = *(const ulonglong2*)&As[kk][ty * 12];
            ulonglong2 aP1 = *(const ulonglong2*)&As[kk][ty * 12 + 4];
            ulonglong2 aP2 = *(const ulonglong2*)&As[kk][ty * 12 + 8];
            unsigned long long ap[6] = { aP0.x, aP0.y, aP1.x, aP1.y, aP2.x, aP2.y };
            // B scalars: 3 x 8B loads, replicate into both f32x2 lanes (ALU pipe)
            float2 b01 = *(const float2*)&Bs[kk][tx * 6];
            float2 b23 = *(const float2*)&Bs[kk][tx * 6 + 2];
            float2 b45 = *(const float2*)&Bs[kk][tx * 6 + 4];
            float bsc[6] = { b01.x, b01.y, b23.x, b23.y, b45.x, b45.y };
            unsigned long long bp[6];
#pragma unroll
            for (int c = 0; c < 6; c++)
                asm("mov.b64 %0, {%1, %1};" : "=l"(bp[c]) : "f"(bsc[c]));
#pragma unroll
            for (int r = 0; r < 6; r++)
#pragma unroll
                for (int c = 0; c < 6; c++)
                    asm("fma.rn.f32x2 %0, %1, %2, %3;"
                        : "=l"(acc[r][c]) : "l"(ap[r]), "l"(bp[c]), "l"(acc[r][c]));
        }
        __syncthreads();
    }

    // --- epilogue ---
#pragma unroll
    for (int r = 0; r < 6; r++) {
        int gr0 = rowBase + ty * 12 + 2 * r;
#pragma unroll
        for (int c = 0; c < 6; c++) {
            U64F2 u; u.u = acc[r][c];
            int gc = colBase + tx * 6 + c;
            if (gr0 < M)     C[(size_t)gr0 * Nc + gc]       = u.f.x;
            if (gr0 + 1 < M) C[(size_t)(gr0 + 1) * Nc + gc] = u.f.y;
        }
    }
}

// ================= attention scalars ======================================
__global__ void calc_a(const float* __restrict__ h, const float* __restrict__ att_src,
                       const float* __restrict__ att_dst, int H) {
    int i = blockIdx.x * blockDim.x + threadIdx.x;  // n*H + hh
    if (i >= NNODES * H) return;
    int hh = i % H, n = i / H;
    const float4* hp = (const float4*)(h + (size_t)n * H * DHEAD + hh * DHEAD);
    const float4* as = (const float4*)(att_src + hh * DHEAD);
    const float4* ad = (const float4*)(att_dst + hh * DHEAD);
    float s = 0.f, d = 0.f;
#pragma unroll
    for (int q = 0; q < DHEAD / 4; q++) {
        float4 hv = hp[q], a = as[q], b = ad[q];
        s += hv.x * a.x + hv.y * a.y + hv.z * a.z + hv.w * a.w;
        d += hv.x * b.x + hv.y * b.y + hv.z * b.z + hv.w * b.w;
    }
    g_asrc[i] = s;
    g_adst[i] = d;
}

// ================= fused softmax over incoming edges (CSR, no atomics) ====
__global__ void attn_softmax(int H) {
    int i = blockIdx.x * blockDim.x + threadIdx.x;  // n*H + hh
    if (i >= NNODES * H) return;
    int n = i / H, hh = i - n * H;
    int start = g_off[n], end = g_off[n + 1];
    float ad = g_adst[i];
    float m = -1e30f;
    for (int p = start; p < end; p++) {
        float v = g_asrc[g_cs[p] * H + hh] + ad;
        v = (v > 0.f) ? v : 0.2f * v;
        m = fmaxf(m, v);
    }
    float sum = 0.f;
    for (int p = start; p < end; p++) {
        float v = g_asrc[g_cs[p] * H + hh] + ad;
        v = (v > 0.f) ? v : 0.2f * v;
        float w = __expf(v - m);
        g_ew[(size_t)p * H + hh] = w;
        sum += w;
    }
    g_denom[i] = 1.f / (sum + 1e-16f);
}

// ================= gather aggregation + bias + relu (no atomics) ==========
__global__ void aggregate(const float* __restrict__ h, float* __restrict__ out,
                          const float* __restrict__ bias, int HD, int H, int total) {
    int idx = blockIdx.x * blockDim.x + threadIdx.x;  // n * (HD/4) + j4
    if (idx >= total) return;
    int nj = HD >> 2;
    int n = idx / nj;
    int j = (idx - n * nj) << 2;
    int head = j / DHEAD;
    int start = g_off[n], end = g_off[n + 1];
    float4 acc = make_float4(0.f, 0.f, 0.f, 0.f);
    for (int p = start; p < end; p++) {
        int s = g_cs[p];
        float w = g_ew[(size_t)p * H + head];
        float4 hv = *(const float4*)(h + (size_t)s * HD + j);
        acc.x += hv.x * w; acc.y += hv.y * w; acc.z += hv.z * w; acc.w += hv.w * w;
    }
    float inv = g_denom[n * H + head];
    float4 b4 = *(const float4*)(bias + j);
    float4 o;
    o.x = fmaxf(acc.x * inv + b4.x, 0.f);
    o.y = fmaxf(acc.y * inv + b4.y, 0.f);
    o.z = fmaxf(acc.z * inv + b4.z, 0.f);
    o.w = fmaxf(acc.w * inv + b4.w, 0.f);
    *(float4*)(out + (size_t)n * HD + j) = o;
}

// ================= pooling + MLP ==========================================
__global__ void pool_kernel(const float* __restrict__ x, const int* __restrict__ batch) {
    int idx = blockIdx.x * blockDim.x + threadIdx.x;  // n * 24 + j4
    int n = idx / (OUTDIM / 4);
    if (n >= NNODES) return;
    int j = (idx - n * (OUTDIM / 4)) << 2;
    int b = batch[n];
    float4 v = *(const float4*)(x + (size_t)n * OUTDIM + j);
    red_add_v4(&g_sums[b * OUTDIM + j], v);
    if (j == 0) atomicAdd(&g_cnt[b], 1.f);
}

__global__ void fc_kernel(const float* __restrict__ fcW1, const float* __restrict__ fcb1,
                          const float* __restrict__ fcW2, const float* __restrict__ fcb2,
                          float* __restrict__ out) {
    __shared__ float pooled[OUTDIM];
    __shared__ float h1[FCDIM];
    int g = blockIdx.x, t = threadIdx.x;  // 192 threads
    if (t < OUTDIM) {
        float c = fmaxf(g_cnt[g], 1.f);
        pooled[t] = g_sums[g * OUTDIM + t] / c;
    }
    __syncthreads();
    float acc = fcb1[t];
    for (int i = 0; i < OUTDIM; i++) acc += pooled[i] * fcW1[(size_t)i * FCDIM + t];
    h1[t] = fmaxf(acc, 0.f);
    __syncthreads();
    if (t < OUTDIM) {
        float a = fcb2[t];
        for (int i = 0; i < FCDIM; i++) a += h1[i] * fcW2[(size_t)i * OUTDIM + t];
        out[g * OUTDIM + t] = a;
    }
}

// ==========================================================================
extern "C" void kernel_launch(void* const* d_in, const int* in_sizes, int n_in,
                              void* d_out, int out_size) {
    const float* x     = (const float*)d_in[0];
    const int*   ei    = (const int*)d_in[1];     // int32 (JAX x64 disabled)
    const int*   batch = (const int*)d_in[2];     // int32
    const float* W[3]    = { (const float*)d_in[3],  (const float*)d_in[7],  (const float*)d_in[11] };
    const float* asv[3]  = { (const float*)d_in[4],  (const float*)d_in[8],  (const float*)d_in[12] };
    const float* adv[3]  = { (const float*)d_in[5],  (const float*)d_in[9],  (const float*)d_in[13] };
    const float* bias[3] = { (const float*)d_in[6],  (const float*)d_in[10], (const float*)d_in[14] };
    const float* fcW1 = (const float*)d_in[15];
    const float* fcb1 = (const float*)d_in[16];
    const float* fcW2 = (const float*)d_in[17];
    const float* fcb2 = (const float*)d_in[18];
    float* out = (float*)d_out;

    const int H[3]   = { 4, 2, 2 };
    const int INC[3] = { 128, 192, 96 };
    const int HD[3]  = { 192, 96, 96 };

    float *bufA, *bufB, *sums, *cnt;
    int *deg, *cursor;
    cudaGetSymbolAddress((void**)&bufA,   g_bufA);
    cudaGetSymbolAddress((void**)&bufB,   g_bufB);
    cudaGetSymbolAddress((void**)&sums,   g_sums);
    cudaGetSymbolAddress((void**)&cnt,    g_cnt);
    cudaGetSymbolAddress((void**)&deg,    g_deg);
    cudaGetSymbolAddress((void**)&cursor, g_cursor);

    // ---- CSR build (once per launch; reused by all 3 layers) ----
    cudaMemsetAsync(deg,    0, NNODES * sizeof(int));
    cudaMemsetAsync(cursor, 0, NNODES * sizeof(int));
    conv_edges<<<(ET + 255) / 256, 256>>>(ei);
    scan_local<<<NSCANB, SCAN_B>>>();
    scan_block<<<1, 1>>>();
    scan_add<<<NSCANB, SCAN_B>>>();
    scatter_edges<<<(ET + 255) / 256, 256>>>();

    const float* xin = x;
    for (int l = 0; l < 3; l++) {
        dim3 grid((NNODES + BM - 1) / BM, HD[l] / BN);
        sgemm_f32x2<<<grid, 256>>>(xin, W[l], bufA, NNODES, INC[l], HD[l]);

        calc_a<<<(NNODES * H[l] + 255) / 256, 256>>>(bufA, asv[l], adv[l], H[l]);

        attn_softmax<<<(NNODES * H[l] + 255) / 256, 256>>>(H[l]);

        int total = NNODES * (HD[l] / 4);
        aggregate<<<(total + 255) / 256, 256>>>(bufA, bufB, bias[l], HD[l], H[l], total);

        xin = bufB;
    }

    cudaMemsetAsync(sums, 0, GBATCH * OUTDIM * sizeof(float));
    cudaMemsetAsync(cnt,  0, GBATCH * sizeof(float));
    int totalP = NNODES * (OUTDIM / 4);
    pool_kernel<<<(totalP + 255) / 256, 256>>>(bufB, batch);

    fc_kernel<<<GBATCH, FCDIM>>>(fcW1, fcb1, fcW2, fcb2, out);
}